// round 6
// baseline (speedup 1.0000x reference)
#include <cuda_runtime.h>
#include <cstdint>

#define N_NODES 100000
#define F_IN    512
#define HID     16
#define N_CLS   40
#define E_EDGES 3200000

#define SCAN_TB   256
#define SCAN_NBLK ((N_NODES + SCAN_TB - 1) / SCAN_TB)   // 391

// packed fp32x2 FMA (Blackwell): d = a*b + c elementwise on 2 packed floats
#define FMA2(d, a, b, c) \
    asm("fma.rn.f32x2 %0, %1, %2, %3;" : "=l"(d) : "l"(a), "l"(b), "l"(c))

// -------- device scratch (no dynamic allocation allowed) --------
__device__ __align__(16) int   g_deg [N_NODES];
__device__ __align__(16) float g_dinv[N_NODES];
__device__ __align__(16) int   g_off [N_NODES + 1];
__device__ __align__(16) int   g_cur [N_NODES];
__device__ __align__(16) int   g_bsum[SCAN_NBLK];
__device__ __align__(16) int   g_bpre[SCAN_NBLK];
__device__ __align__(16) int2  g_csr [E_EDGES];          // (src, weight bits)
__device__ __align__(16) float g_h1  [N_NODES * HID];
__device__ __align__(16) float g_out1[N_NODES * HID];

// -------- degree / norm --------
__global__ void init_deg_kernel() {
    int i = blockIdx.x * blockDim.x + threadIdx.x;
    if (i < N_NODES) g_deg[i] = 1;  // self loop
}

__global__ void hist_kernel(const int* __restrict__ ei) {
    int e = blockIdx.x * blockDim.x + threadIdx.x;
    if (e < E_EDGES) atomicAdd(&g_deg[ei[E_EDGES + e]], 1);
}

__global__ void dinv_kernel() {
    int i = blockIdx.x * blockDim.x + threadIdx.x;
    if (i < N_NODES) g_dinv[i] = rsqrtf((float)g_deg[i]);
}

// -------- CSR prefix scan (counts = deg - 1, i.e. edges only) --------
__global__ void scan_bsum_kernel() {
    __shared__ int sh[SCAN_TB];
    int i = blockIdx.x * SCAN_TB + threadIdx.x;
    sh[threadIdx.x] = (i < N_NODES) ? (g_deg[i] - 1) : 0;
    __syncthreads();
    for (int s = SCAN_TB / 2; s > 0; s >>= 1) {
        if (threadIdx.x < s) sh[threadIdx.x] += sh[threadIdx.x + s];
        __syncthreads();
    }
    if (threadIdx.x == 0) g_bsum[blockIdx.x] = sh[0];
}

// single block, 512 threads: exclusive scan over SCAN_NBLK block sums
__global__ void scan_bpre_kernel() {
    __shared__ int sh[2][512];
    int t = threadIdx.x;
    int c = (t < SCAN_NBLK) ? g_bsum[t] : 0;
    int buf = 0;
    sh[0][t] = c;
    __syncthreads();
    #pragma unroll
    for (int s = 1; s < 512; s <<= 1) {
        int v = sh[buf][t];
        if (t >= s) v += sh[buf][t - s];
        sh[buf ^ 1][t] = v;
        buf ^= 1;
        __syncthreads();
    }
    if (t < SCAN_NBLK) g_bpre[t] = sh[buf][t] - c;   // exclusive
    if (t == 0) g_off[N_NODES] = E_EDGES;
}

__global__ void scan_off_kernel() {
    __shared__ int sh[2][SCAN_TB];
    int i = blockIdx.x * SCAN_TB + threadIdx.x;
    int c = (i < N_NODES) ? (g_deg[i] - 1) : 0;
    int buf = 0;
    sh[0][threadIdx.x] = c;
    __syncthreads();
    #pragma unroll
    for (int s = 1; s < SCAN_TB; s <<= 1) {
        int v = sh[buf][threadIdx.x];
        if (threadIdx.x >= s) v += sh[buf][threadIdx.x - s];
        sh[buf ^ 1][threadIdx.x] = v;
        buf ^= 1;
        __syncthreads();
    }
    if (i < N_NODES) {
        int off = g_bpre[blockIdx.x] + sh[buf][threadIdx.x] - c;  // exclusive
        g_off[i] = off;
        g_cur[i] = off;
    }
}

// -------- CSR fill: (src, norm-weight) per dst bucket --------
__global__ void fill_kernel(const int* __restrict__ ei) {
    int e = blockIdx.x * blockDim.x + threadIdx.x;
    if (e >= E_EDGES) return;
    int s = ei[e];
    int d = ei[E_EDGES + e];
    int pos = atomicAdd(&g_cur[d], 1);
    float w = g_dinv[s] * g_dinv[d];
    g_csr[pos] = make_int2(s, __float_as_int(w));
}

// -------- GEMM1: h1 = x @ W1  (100000x512 @ 512x16) --------
// 16 rows per warp for MLP; lane = (j, half); packed f32x2 accumulators.
#define R_PW 16
__global__ __launch_bounds__(256) void gemm1_kernel(const float* __restrict__ x,
                                                    const float* __restrict__ W1) {
    __shared__ float Ws[HID][F_IN + 4];  // transposed, padded
    for (int i = threadIdx.x; i < F_IN * HID; i += blockDim.x) {
        int k = i >> 4;
        int j = i & 15;
        Ws[j][k] = W1[i];
    }
    __syncthreads();

    int warp_id = (blockIdx.x * blockDim.x + threadIdx.x) >> 5;
    int lane    = threadIdx.x & 31;
    int j       = lane & 15;
    int half    = lane >> 4;
    size_t row0 = (size_t)warp_id * R_PW;
    if (row0 >= N_NODES) return;

    unsigned long long acc2[R_PW];
    #pragma unroll
    for (int r = 0; r < R_PW; r++) acc2[r] = 0ull;

    const float* xb   = x + row0 * F_IN + half * 256;
    const float* wrow = &Ws[j][half * 256];

    for (int kk = 0; kk < 256; kk += 4) {
        ulonglong2 w2 = *reinterpret_cast<const ulonglong2*>(wrow + kk);
        #pragma unroll
        for (int r = 0; r < R_PW; r++) {
            ulonglong2 xv = *reinterpret_cast<const ulonglong2*>(xb + (size_t)r * F_IN + kk);
            FMA2(acc2[r], xv.x, w2.x, acc2[r]);
            FMA2(acc2[r], xv.y, w2.y, acc2[r]);
        }
    }
    #pragma unroll
    for (int r = 0; r < R_PW; r++) {
        float lo = __uint_as_float((unsigned)(acc2[r] & 0xffffffffull));
        float hi = __uint_as_float((unsigned)(acc2[r] >> 32));
        float acc = lo + hi;
        acc += __shfl_xor_sync(0xffffffffu, acc, 16);
        if (lane < 16) g_h1[(row0 + r) * HID + j] = acc;
    }
}

// -------- layer-1 pull aggregation + bias + relu -> g_out1 --------
__global__ void gather1_kernel(const float* __restrict__ b1) {
    int warp = (blockIdx.x * blockDim.x + threadIdx.x) >> 5;
    if (warp >= N_NODES) return;
    int lane = threadIdx.x & 31;
    int j = lane & 15;
    int p = lane >> 4;

    int beg = g_off[warp];
    int end = g_off[warp + 1];

    float a0 = 0.f, a1 = 0.f, a2 = 0.f, a3 = 0.f;
    int e = beg + p;
    for (; e + 6 < end; e += 8) {
        int2 r0 = g_csr[e];
        int2 r1 = g_csr[e + 2];
        int2 r2 = g_csr[e + 4];
        int2 r3 = g_csr[e + 6];
        a0 = fmaf(g_h1[(size_t)r0.x * HID + j], __int_as_float(r0.y), a0);
        a1 = fmaf(g_h1[(size_t)r1.x * HID + j], __int_as_float(r1.y), a1);
        a2 = fmaf(g_h1[(size_t)r2.x * HID + j], __int_as_float(r2.y), a2);
        a3 = fmaf(g_h1[(size_t)r3.x * HID + j], __int_as_float(r3.y), a3);
    }
    for (; e < end; e += 2) {
        int2 r0 = g_csr[e];
        a0 = fmaf(g_h1[(size_t)r0.x * HID + j], __int_as_float(r0.y), a0);
    }
    float acc = (a0 + a1) + (a2 + a3);
    acc += __shfl_xor_sync(0xffffffffu, acc, 16);

    if (p == 0) {
        float dv = g_dinv[warp];
        acc = fmaf(g_h1[(size_t)warp * HID + j], dv * dv, acc);  // self loop
        acc = fmaxf(acc + b1[j], 0.f);                           // bias + relu
        g_out1[(size_t)warp * HID + j] = acc;
    }
}

// -------- layer-2 aggregation fused with GEMM2 + bias + log_softmax --------
__global__ void gather2_softmax_kernel(const float* __restrict__ W2,
                                       const float* __restrict__ b2,
                                       float* __restrict__ out) {
    __shared__ float W2s[HID * N_CLS];
    __shared__ float b2s[N_CLS];
    for (int i = threadIdx.x; i < HID * N_CLS; i += blockDim.x) W2s[i] = W2[i];
    if (threadIdx.x < N_CLS) b2s[threadIdx.x] = b2[threadIdx.x];
    __syncthreads();

    int warp = (blockIdx.x * blockDim.x + threadIdx.x) >> 5;
    if (warp >= N_NODES) return;
    int lane = threadIdx.x & 31;
    int j = lane & 15;
    int p = lane >> 4;

    int beg = g_off[warp];
    int end = g_off[warp + 1];

    float a0 = 0.f, a1 = 0.f, a2 = 0.f, a3 = 0.f;
    int e = beg + p;
    for (; e + 6 < end; e += 8) {
        int2 r0 = g_csr[e];
        int2 r1 = g_csr[e + 2];
        int2 r2 = g_csr[e + 4];
        int2 r3 = g_csr[e + 6];
        a0 = fmaf(g_out1[(size_t)r0.x * HID + j], __int_as_float(r0.y), a0);
        a1 = fmaf(g_out1[(size_t)r1.x * HID + j], __int_as_float(r1.y), a1);
        a2 = fmaf(g_out1[(size_t)r2.x * HID + j], __int_as_float(r2.y), a2);
        a3 = fmaf(g_out1[(size_t)r3.x * HID + j], __int_as_float(r3.y), a3);
    }
    for (; e < end; e += 2) {
        int2 r0 = g_csr[e];
        a0 = fmaf(g_out1[(size_t)r0.x * HID + j], __int_as_float(r0.y), a0);
    }
    float av = (a0 + a1) + (a2 + a3);
    av += __shfl_xor_sync(0xffffffffu, av, 16);   // both halves now hold full sum
    float dv = g_dinv[warp];
    av = fmaf(g_out1[(size_t)warp * HID + j], dv * dv, av);  // self loop

    // av[j] replicated on lanes j and j+16. mat-vec 16x40 + log_softmax.
    bool act = lane < 20;
    int  j0  = act ? lane : 0;

    float z0 = 0.f, z1 = 0.f;
    #pragma unroll
    for (int k = 0; k < HID; k++) {
        float ak = __shfl_sync(0xffffffffu, av, k);   // lane k holds av[k]
        z0 = fmaf(ak, W2s[k * N_CLS + j0],      z0);
        z1 = fmaf(ak, W2s[k * N_CLS + j0 + 20], z1);
    }
    z0 += b2s[j0];
    z1 += b2s[j0 + 20];

    float m = act ? fmaxf(z0, z1) : -INFINITY;
    #pragma unroll
    for (int o = 16; o; o >>= 1) m = fmaxf(m, __shfl_xor_sync(0xffffffffu, m, o));
    float s = act ? (expf(z0 - m) + expf(z1 - m)) : 0.f;
    #pragma unroll
    for (int o = 16; o; o >>= 1) s += __shfl_xor_sync(0xffffffffu, s, o);
    float lse = m + logf(s);

    if (act) {
        out[(size_t)warp * N_CLS + lane]      = z0 - lse;
        out[(size_t)warp * N_CLS + lane + 20] = z1 - lse;
    }
}

// -------- launch --------
extern "C" void kernel_launch(void* const* d_in, const int* in_sizes, int n_in,
                              void* d_out, int out_size) {
    const float* x  = (const float*)d_in[0];
    const int*   ei = (const int*)d_in[1];     // int32 (JAX x64 disabled)
    const float* W1 = (const float*)d_in[2];
    const float* b1 = (const float*)d_in[3];
    const float* W2 = (const float*)d_in[4];
    const float* b2 = (const float*)d_in[5];
    float* out = (float*)d_out;

    const int TB = 256;
    int nblk_nodes = (N_NODES + TB - 1) / TB;
    int nblk_edges = (E_EDGES + TB - 1) / TB;
    int nwarps_g1  = (N_NODES + R_PW - 1) / R_PW;
    int nblk_gemm1 = (nwarps_g1 + (TB / 32) - 1) / (TB / 32);
    int nblk_rows  = (N_NODES + (TB / 32) - 1) / (TB / 32);  // warp per node

    init_deg_kernel<<<nblk_nodes, TB>>>();
    hist_kernel<<<nblk_edges, TB>>>(ei);
    dinv_kernel<<<nblk_nodes, TB>>>();

    scan_bsum_kernel<<<SCAN_NBLK, SCAN_TB>>>();
    scan_bpre_kernel<<<1, 512>>>();
    scan_off_kernel<<<SCAN_NBLK, SCAN_TB>>>();
    fill_kernel<<<nblk_edges, TB>>>(ei);

    gemm1_kernel<<<nblk_gemm1, TB>>>(x, W1);

    gather1_kernel<<<nblk_rows, TB>>>(b1);
    gather2_softmax_kernel<<<nblk_rows, TB>>>(W2, b2, out);
}

// round 7
// speedup vs baseline: 1.0524x; 1.0524x over previous
#include <cuda_runtime.h>
#include <cstdint>

#define N_NODES 100000
#define F_IN    512
#define HID     16
#define N_CLS   40
#define E_EDGES 3200000

#define SCAN_TB   256
#define SCAN_NBLK ((N_NODES + SCAN_TB - 1) / SCAN_TB)   // 391

// packed fp32x2 ops (Blackwell)
#define FMA2(d, a, b, c) \
    asm("fma.rn.f32x2 %0, %1, %2, %3;" : "=l"(d) : "l"(a), "l"(b), "l"(c))
#define ADD2(d, a, b) \
    asm("add.rn.f32x2 %0, %1, %2;" : "=l"(d) : "l"(a), "l"(b))

// -------- device scratch (no dynamic allocation allowed) --------
__device__ __align__(16) int   g_deg [N_NODES];
__device__ __align__(16) float g_dinv[N_NODES];
__device__ __align__(16) int   g_off [N_NODES + 1];
__device__ __align__(16) int   g_cur [N_NODES];
__device__ __align__(16) int   g_bsum[SCAN_NBLK];
__device__ __align__(16) int   g_bpre[SCAN_NBLK];
__device__ __align__(16) int2  g_csr [E_EDGES];          // (src, weight bits)
__device__ __align__(16) float g_h1  [N_NODES * HID];
__device__ __align__(16) float g_out1[N_NODES * HID];

// -------- degree / norm --------
__global__ void init_deg_kernel() {
    int i = blockIdx.x * blockDim.x + threadIdx.x;
    if (i < N_NODES) g_deg[i] = 1;  // self loop
}

__global__ void hist_kernel(const int* __restrict__ ei) {
    int e = blockIdx.x * blockDim.x + threadIdx.x;
    if (e < E_EDGES) atomicAdd(&g_deg[ei[E_EDGES + e]], 1);
}

__global__ void dinv_kernel() {
    int i = blockIdx.x * blockDim.x + threadIdx.x;
    if (i < N_NODES) g_dinv[i] = rsqrtf((float)g_deg[i]);
}

// -------- GEMM1: h1 = x @ W1  (100000x512 @ 512x16), coalesced --------
// Warp handles 4 rows. Lane owns k = it*32 + lane (it = 0..15).
// x loads: LDG.32, 128B unique per warp-instruction (fully coalesced).
// W from smem, stride-20 padding -> conflict-free LDS.128.
#define G1_R 4
__global__ __launch_bounds__(256) void gemm1_kernel(const float* __restrict__ x,
                                                    const float* __restrict__ W1) {
    __shared__ float Wp[F_IN * 20];   // 40 KB
    for (int i = threadIdx.x; i < F_IN * HID; i += 256) {
        int k = i >> 4;
        int j = i & 15;
        Wp[k * 20 + j] = W1[i];
    }
    __syncthreads();

    int warp = threadIdx.x >> 5;
    int lane = threadIdx.x & 31;
    size_t row0 = (size_t)blockIdx.x * (8 * G1_R) + warp * G1_R;   // 32 rows/block
    const float* xb = x + row0 * F_IN + lane;

    unsigned long long acc2[G1_R][8];
    #pragma unroll
    for (int r = 0; r < G1_R; r++)
        #pragma unroll
        for (int q = 0; q < 8; q++) acc2[r][q] = 0ull;

    #pragma unroll 4
    for (int it = 0; it < 16; it++) {
        int k = it * 32 + lane;
        // x values for the 4 rows (independent coalesced loads)
        float xv[G1_R];
        #pragma unroll
        for (int r = 0; r < G1_R; r++)
            xv[r] = xb[(size_t)r * F_IN + it * 32];

        // W[k][0..15] as 8 packed f32x2 (4x LDS.128, conflict-free)
        const float* wk = &Wp[k * 20];
        ulonglong2 wa = *reinterpret_cast<const ulonglong2*>(wk);
        ulonglong2 wb = *reinterpret_cast<const ulonglong2*>(wk + 4);
        ulonglong2 wc = *reinterpret_cast<const ulonglong2*>(wk + 8);
        ulonglong2 wd = *reinterpret_cast<const ulonglong2*>(wk + 12);

        #pragma unroll
        for (int r = 0; r < G1_R; r++) {
            unsigned xu = __float_as_uint(xv[r]);
            unsigned long long x2;
            asm("mov.b64 %0, {%1, %1};" : "=l"(x2) : "r"(xu));
            FMA2(acc2[r][0], x2, wa.x, acc2[r][0]);
            FMA2(acc2[r][1], x2, wa.y, acc2[r][1]);
            FMA2(acc2[r][2], x2, wb.x, acc2[r][2]);
            FMA2(acc2[r][3], x2, wb.y, acc2[r][3]);
            FMA2(acc2[r][4], x2, wc.x, acc2[r][4]);
            FMA2(acc2[r][5], x2, wc.y, acc2[r][5]);
            FMA2(acc2[r][6], x2, wd.x, acc2[r][6]);
            FMA2(acc2[r][7], x2, wd.y, acc2[r][7]);
        }
    }

    // reduce across 32 lanes (packed f32x2 butterfly), store 16 outputs/row
    #pragma unroll
    for (int r = 0; r < G1_R; r++) {
        #pragma unroll
        for (int s = 16; s; s >>= 1) {
            #pragma unroll
            for (int q = 0; q < 8; q++) {
                unsigned lo = (unsigned)acc2[r][q];
                unsigned hi = (unsigned)(acc2[r][q] >> 32);
                lo = __shfl_xor_sync(0xffffffffu, lo, s);
                hi = __shfl_xor_sync(0xffffffffu, hi, s);
                unsigned long long other = ((unsigned long long)hi << 32) | lo;
                ADD2(acc2[r][q], acc2[r][q], other);
            }
        }
        if (lane < 16) {
            unsigned long long v = acc2[r][lane >> 1];
            float f = (lane & 1) ? __uint_as_float((unsigned)(v >> 32))
                                 : __uint_as_float((unsigned)v);
            g_h1[(row0 + r) * HID + lane] = f;
        }
    }
}

// -------- CSR prefix scan (counts = deg - 1, i.e. edges only) --------
__global__ void scan_bsum_kernel() {
    __shared__ int sh[SCAN_TB];
    int i = blockIdx.x * SCAN_TB + threadIdx.x;
    sh[threadIdx.x] = (i < N_NODES) ? (g_deg[i] - 1) : 0;
    __syncthreads();
    for (int s = SCAN_TB / 2; s > 0; s >>= 1) {
        if (threadIdx.x < s) sh[threadIdx.x] += sh[threadIdx.x + s];
        __syncthreads();
    }
    if (threadIdx.x == 0) g_bsum[blockIdx.x] = sh[0];
}

// single block, 512 threads: exclusive scan over SCAN_NBLK block sums
__global__ void scan_bpre_kernel() {
    __shared__ int sh[2][512];
    int t = threadIdx.x;
    int c = (t < SCAN_NBLK) ? g_bsum[t] : 0;
    int buf = 0;
    sh[0][t] = c;
    __syncthreads();
    #pragma unroll
    for (int s = 1; s < 512; s <<= 1) {
        int v = sh[buf][t];
        if (t >= s) v += sh[buf][t - s];
        sh[buf ^ 1][t] = v;
        buf ^= 1;
        __syncthreads();
    }
    if (t < SCAN_NBLK) g_bpre[t] = sh[buf][t] - c;   // exclusive
    if (t == 0) g_off[N_NODES] = E_EDGES;
}

__global__ void scan_off_kernel() {
    __shared__ int sh[2][SCAN_TB];
    int i = blockIdx.x * SCAN_TB + threadIdx.x;
    int c = (i < N_NODES) ? (g_deg[i] - 1) : 0;
    int buf = 0;
    sh[0][threadIdx.x] = c;
    __syncthreads();
    #pragma unroll
    for (int s = 1; s < SCAN_TB; s <<= 1) {
        int v = sh[buf][threadIdx.x];
        if (threadIdx.x >= s) v += sh[buf][threadIdx.x - s];
        sh[buf ^ 1][threadIdx.x] = v;
        buf ^= 1;
        __syncthreads();
    }
    if (i < N_NODES) {
        int off = g_bpre[blockIdx.x] + sh[buf][threadIdx.x] - c;  // exclusive
        g_off[i] = off;
        g_cur[i] = off;
    }
}

// -------- CSR fill: (src, norm-weight) per dst bucket --------
__global__ void fill_kernel(const int* __restrict__ ei) {
    int e = blockIdx.x * blockDim.x + threadIdx.x;
    if (e >= E_EDGES) return;
    int s = ei[e];
    int d = ei[E_EDGES + e];
    int pos = atomicAdd(&g_cur[d], 1);
    float w = g_dinv[s] * g_dinv[d];
    g_csr[pos] = make_int2(s, __float_as_int(w));
}

// -------- layer-1 pull aggregation + bias + relu -> g_out1 --------
__global__ void gather1_kernel(const float* __restrict__ b1) {
    int warp = (blockIdx.x * blockDim.x + threadIdx.x) >> 5;
    if (warp >= N_NODES) return;
    int lane = threadIdx.x & 31;
    int j = lane & 15;
    int p = lane >> 4;

    int beg = g_off[warp];
    int end = g_off[warp + 1];

    float a0 = 0.f, a1 = 0.f, a2 = 0.f, a3 = 0.f;
    int e = beg + p;
    for (; e + 6 < end; e += 8) {
        int2 r0 = g_csr[e];
        int2 r1 = g_csr[e + 2];
        int2 r2 = g_csr[e + 4];
        int2 r3 = g_csr[e + 6];
        a0 = fmaf(g_h1[(size_t)r0.x * HID + j], __int_as_float(r0.y), a0);
        a1 = fmaf(g_h1[(size_t)r1.x * HID + j], __int_as_float(r1.y), a1);
        a2 = fmaf(g_h1[(size_t)r2.x * HID + j], __int_as_float(r2.y), a2);
        a3 = fmaf(g_h1[(size_t)r3.x * HID + j], __int_as_float(r3.y), a3);
    }
    for (; e < end; e += 2) {
        int2 r0 = g_csr[e];
        a0 = fmaf(g_h1[(size_t)r0.x * HID + j], __int_as_float(r0.y), a0);
    }
    float acc = (a0 + a1) + (a2 + a3);
    acc += __shfl_xor_sync(0xffffffffu, acc, 16);

    if (p == 0) {
        float dv = g_dinv[warp];
        acc = fmaf(g_h1[(size_t)warp * HID + j], dv * dv, acc);  // self loop
        acc = fmaxf(acc + b1[j], 0.f);                           // bias + relu
        g_out1[(size_t)warp * HID + j] = acc;
    }
}

// -------- layer-2 aggregation fused with GEMM2 + bias + log_softmax --------
__global__ void gather2_softmax_kernel(const float* __restrict__ W2,
                                       const float* __restrict__ b2,
                                       float* __restrict__ out) {
    __shared__ float W2s[HID * N_CLS];
    __shared__ float b2s[N_CLS];
    for (int i = threadIdx.x; i < HID * N_CLS; i += blockDim.x) W2s[i] = W2[i];
    if (threadIdx.x < N_CLS) b2s[threadIdx.x] = b2[threadIdx.x];
    __syncthreads();

    int warp = (blockIdx.x * blockDim.x + threadIdx.x) >> 5;
    if (warp >= N_NODES) return;
    int lane = threadIdx.x & 31;
    int j = lane & 15;
    int p = lane >> 4;

    int beg = g_off[warp];
    int end = g_off[warp + 1];

    float a0 = 0.f, a1 = 0.f, a2 = 0.f, a3 = 0.f;
    int e = beg + p;
    for (; e + 6 < end; e += 8) {
        int2 r0 = g_csr[e];
        int2 r1 = g_csr[e + 2];
        int2 r2 = g_csr[e + 4];
        int2 r3 = g_csr[e + 6];
        a0 = fmaf(g_out1[(size_t)r0.x * HID + j], __int_as_float(r0.y), a0);
        a1 = fmaf(g_out1[(size_t)r1.x * HID + j], __int_as_float(r1.y), a1);
        a2 = fmaf(g_out1[(size_t)r2.x * HID + j], __int_as_float(r2.y), a2);
        a3 = fmaf(g_out1[(size_t)r3.x * HID + j], __int_as_float(r3.y), a3);
    }
    for (; e < end; e += 2) {
        int2 r0 = g_csr[e];
        a0 = fmaf(g_out1[(size_t)r0.x * HID + j], __int_as_float(r0.y), a0);
    }
    float av = (a0 + a1) + (a2 + a3);
    av += __shfl_xor_sync(0xffffffffu, av, 16);   // both halves now hold full sum
    float dv = g_dinv[warp];
    av = fmaf(g_out1[(size_t)warp * HID + j], dv * dv, av);  // self loop

    // av[j] replicated on lanes j and j+16. mat-vec 16x40 + log_softmax.
    bool act = lane < 20;
    int  j0  = act ? lane : 0;

    float z0 = 0.f, z1 = 0.f;
    #pragma unroll
    for (int k = 0; k < HID; k++) {
        float ak = __shfl_sync(0xffffffffu, av, k);   // lane k holds av[k]
        z0 = fmaf(ak, W2s[k * N_CLS + j0],      z0);
        z1 = fmaf(ak, W2s[k * N_CLS + j0 + 20], z1);
    }
    z0 += b2s[j0];
    z1 += b2s[j0 + 20];

    float m = act ? fmaxf(z0, z1) : -INFINITY;
    #pragma unroll
    for (int o = 16; o; o >>= 1) m = fmaxf(m, __shfl_xor_sync(0xffffffffu, m, o));
    float s = act ? (expf(z0 - m) + expf(z1 - m)) : 0.f;
    #pragma unroll
    for (int o = 16; o; o >>= 1) s += __shfl_xor_sync(0xffffffffu, s, o);
    float lse = m + logf(s);

    if (act) {
        out[(size_t)warp * N_CLS + lane]      = z0 - lse;
        out[(size_t)warp * N_CLS + lane + 20] = z1 - lse;
    }
}

// -------- launch --------
extern "C" void kernel_launch(void* const* d_in, const int* in_sizes, int n_in,
                              void* d_out, int out_size) {
    const float* x  = (const float*)d_in[0];
    const int*   ei = (const int*)d_in[1];     // int32 (JAX x64 disabled)
    const float* W1 = (const float*)d_in[2];
    const float* b1 = (const float*)d_in[3];
    const float* W2 = (const float*)d_in[4];
    const float* b2 = (const float*)d_in[5];
    float* out = (float*)d_out;

    const int TB = 256;
    int nblk_nodes = (N_NODES + TB - 1) / TB;
    int nblk_edges = (E_EDGES + TB - 1) / TB;
    int nblk_gemm1 = N_NODES / (8 * G1_R);               // 32 rows per block, exact
    int nblk_rows  = (N_NODES + (TB / 32) - 1) / (TB / 32);  // warp per node

    init_deg_kernel<<<nblk_nodes, TB>>>();
    hist_kernel<<<nblk_edges, TB>>>(ei);
    dinv_kernel<<<nblk_nodes, TB>>>();

    gemm1_kernel<<<nblk_gemm1, TB>>>(x, W1);   // launch #4 -> gets profiled

    scan_bsum_kernel<<<SCAN_NBLK, SCAN_TB>>>();
    scan_bpre_kernel<<<1, 512>>>();
    scan_off_kernel<<<SCAN_NBLK, SCAN_TB>>>();
    fill_kernel<<<nblk_edges, TB>>>(ei);

    gather1_kernel<<<nblk_rows, TB>>>(b1);
    gather2_softmax_kernel<<<nblk_rows, TB>>>(W2, b2, out);
}

// round 8
// speedup vs baseline: 1.1734x; 1.1150x over previous
#include <cuda_runtime.h>
#include <cstdint>

#define N_NODES 100000
#define F_IN    512
#define HID     16
#define N_CLS   40
#define E_EDGES 3200000

#define SCAN_TB   256
#define SCAN_NBLK ((N_NODES + SCAN_TB - 1) / SCAN_TB)   // 391

// packed fp32x2 ops (Blackwell)
#define FMA2(d, a, b, c) \
    asm("fma.rn.f32x2 %0, %1, %2, %3;" : "=l"(d) : "l"(a), "l"(b), "l"(c))

// -------- device scratch (no dynamic allocation allowed) --------
__device__ __align__(16) int   g_deg [N_NODES];
__device__ __align__(16) float g_dinv[N_NODES];
__device__ __align__(16) int   g_off [N_NODES + 1];
__device__ __align__(16) int   g_cur [N_NODES];
__device__ __align__(16) int   g_bsum[SCAN_NBLK];
__device__ __align__(16) int   g_bpre[SCAN_NBLK];
__device__ __align__(16) int2  g_csr [E_EDGES];          // (src, weight bits)
__device__ __align__(16) float g_h1  [N_NODES * HID];
__device__ __align__(16) float g_out1[N_NODES * HID];

// -------- degree / norm --------
__global__ void init_deg_kernel() {
    int i = blockIdx.x * blockDim.x + threadIdx.x;
    if (i < N_NODES) g_deg[i] = 1;  // self loop
}

__global__ void hist_kernel(const int* __restrict__ ei) {
    int e = blockIdx.x * blockDim.x + threadIdx.x;
    if (e < E_EDGES) atomicAdd(&g_deg[ei[E_EDGES + e]], 1);
}

__global__ void dinv_kernel() {
    int i = blockIdx.x * blockDim.x + threadIdx.x;
    if (i < N_NODES) g_dinv[i] = rsqrtf((float)g_deg[i]);
}

// -------- GEMM1: h1 = x @ W1  (100000x512 @ 512x16) --------
// Block: 256 threads, 64 rows. x staged in smem (coalesced LDG.128),
// lane = (j, half) accumulates output j over its K-half with packed f32x2.
#define G1_ROWS 64
#define G1_KC   128
#define WS_STRIDE 516                       // conflict-free LDS.128 per-j rows
#define G1_SMEM ((HID * WS_STRIDE + G1_ROWS * G1_KC) * 4)   // 65792 B

__global__ __launch_bounds__(256) void gemm1_kernel(const float* __restrict__ x,
                                                    const float* __restrict__ W1) {
    extern __shared__ float smem[];
    float* Ws = smem;                       // [16][516], Ws[j*516 + k]
    float* xs = smem + HID * WS_STRIDE;     // [64][128]

    // stage full W (transposed) once
    for (int i = threadIdx.x; i < F_IN * HID; i += 256) {
        int k = i >> 4;
        int j = i & 15;
        Ws[j * WS_STRIDE + k] = W1[i];
    }

    int warp = threadIdx.x >> 5;
    int lane = threadIdx.x & 31;
    int j    = lane & 15;
    int half = lane >> 4;
    int row0 = blockIdx.x * G1_ROWS;

    unsigned long long acc[8];
    #pragma unroll
    for (int r = 0; r < 8; r++) acc[r] = 0ull;

    for (int kc = 0; kc < F_IN; kc += G1_KC) {
        __syncthreads();
        // stage x tile: 64 rows x 128 cols, coalesced float4
        #pragma unroll
        for (int i = threadIdx.x; i < G1_ROWS * (G1_KC / 4); i += 256) {
            int row = i >> 5;            // /32 float4 per row
            int c4  = i & 31;
            int grow = row0 + row;
            if (grow >= N_NODES) grow = N_NODES - 1;   // clamp (stores guarded)
            float4 v = *reinterpret_cast<const float4*>(
                x + (size_t)grow * F_IN + kc + c4 * 4);
            *reinterpret_cast<float4*>(&xs[row * G1_KC + c4 * 4]) = v;
        }
        __syncthreads();

        const float* wbase = &Ws[j * WS_STRIDE + kc + half * 64];
        const float* xbase = &xs[warp * 8 * G1_KC + half * 64];

        #pragma unroll
        for (int kk = 0; kk < 64; kk += 4) {
            ulonglong2 w2 = *reinterpret_cast<const ulonglong2*>(wbase + kk);
            #pragma unroll
            for (int r = 0; r < 8; r++) {
                ulonglong2 xv = *reinterpret_cast<const ulonglong2*>(
                    xbase + r * G1_KC + kk);
                FMA2(acc[r], xv.x, w2.x, acc[r]);
                FMA2(acc[r], xv.y, w2.y, acc[r]);
            }
        }
    }

    // finish: unpack pair, add halves via shfl, store
    #pragma unroll
    for (int r = 0; r < 8; r++) {
        float lo = __uint_as_float((unsigned)acc[r]);
        float hi = __uint_as_float((unsigned)(acc[r] >> 32));
        float a = lo + hi;
        a += __shfl_xor_sync(0xffffffffu, a, 16);
        int grow = row0 + warp * 8 + r;
        if (lane < 16 && grow < N_NODES)
            g_h1[(size_t)grow * HID + j] = a;
    }
}

// -------- CSR prefix scan (counts = deg - 1, i.e. edges only) --------
__global__ void scan_bsum_kernel() {
    __shared__ int sh[SCAN_TB];
    int i = blockIdx.x * SCAN_TB + threadIdx.x;
    sh[threadIdx.x] = (i < N_NODES) ? (g_deg[i] - 1) : 0;
    __syncthreads();
    for (int s = SCAN_TB / 2; s > 0; s >>= 1) {
        if (threadIdx.x < s) sh[threadIdx.x] += sh[threadIdx.x + s];
        __syncthreads();
    }
    if (threadIdx.x == 0) g_bsum[blockIdx.x] = sh[0];
}

// single block, 512 threads: exclusive scan over SCAN_NBLK block sums
__global__ void scan_bpre_kernel() {
    __shared__ int sh[2][512];
    int t = threadIdx.x;
    int c = (t < SCAN_NBLK) ? g_bsum[t] : 0;
    int buf = 0;
    sh[0][t] = c;
    __syncthreads();
    #pragma unroll
    for (int s = 1; s < 512; s <<= 1) {
        int v = sh[buf][t];
        if (t >= s) v += sh[buf][t - s];
        sh[buf ^ 1][t] = v;
        buf ^= 1;
        __syncthreads();
    }
    if (t < SCAN_NBLK) g_bpre[t] = sh[buf][t] - c;   // exclusive
    if (t == 0) g_off[N_NODES] = E_EDGES;
}

__global__ void scan_off_kernel() {
    __shared__ int sh[2][SCAN_TB];
    int i = blockIdx.x * SCAN_TB + threadIdx.x;
    int c = (i < N_NODES) ? (g_deg[i] - 1) : 0;
    int buf = 0;
    sh[0][threadIdx.x] = c;
    __syncthreads();
    #pragma unroll
    for (int s = 1; s < SCAN_TB; s <<= 1) {
        int v = sh[buf][threadIdx.x];
        if (threadIdx.x >= s) v += sh[buf][threadIdx.x - s];
        sh[buf ^ 1][threadIdx.x] = v;
        buf ^= 1;
        __syncthreads();
    }
    if (i < N_NODES) {
        int off = g_bpre[blockIdx.x] + sh[buf][threadIdx.x] - c;  // exclusive
        g_off[i] = off;
        g_cur[i] = off;
    }
}

// -------- CSR fill: (src, norm-weight) per dst bucket --------
__global__ void fill_kernel(const int* __restrict__ ei) {
    int e = blockIdx.x * blockDim.x + threadIdx.x;
    if (e >= E_EDGES) return;
    int s = ei[e];
    int d = ei[E_EDGES + e];
    int pos = atomicAdd(&g_cur[d], 1);
    float w = g_dinv[s] * g_dinv[d];
    g_csr[pos] = make_int2(s, __float_as_int(w));
}

// -------- layer-1 pull aggregation + bias + relu -> g_out1 --------
__global__ void gather1_kernel(const float* __restrict__ b1) {
    int warp = (blockIdx.x * blockDim.x + threadIdx.x) >> 5;
    if (warp >= N_NODES) return;
    int lane = threadIdx.x & 31;
    int j = lane & 15;
    int p = lane >> 4;

    int beg = g_off[warp];
    int end = g_off[warp + 1];

    float a0 = 0.f, a1 = 0.f, a2 = 0.f, a3 = 0.f;
    int e = beg + p;
    for (; e + 6 < end; e += 8) {
        int2 r0 = g_csr[e];
        int2 r1 = g_csr[e + 2];
        int2 r2 = g_csr[e + 4];
        int2 r3 = g_csr[e + 6];
        a0 = fmaf(g_h1[(size_t)r0.x * HID + j], __int_as_float(r0.y), a0);
        a1 = fmaf(g_h1[(size_t)r1.x * HID + j], __int_as_float(r1.y), a1);
        a2 = fmaf(g_h1[(size_t)r2.x * HID + j], __int_as_float(r2.y), a2);
        a3 = fmaf(g_h1[(size_t)r3.x * HID + j], __int_as_float(r3.y), a3);
    }
    for (; e < end; e += 2) {
        int2 r0 = g_csr[e];
        a0 = fmaf(g_h1[(size_t)r0.x * HID + j], __int_as_float(r0.y), a0);
    }
    float acc = (a0 + a1) + (a2 + a3);
    acc += __shfl_xor_sync(0xffffffffu, acc, 16);

    if (p == 0) {
        float dv = g_dinv[warp];
        acc = fmaf(g_h1[(size_t)warp * HID + j], dv * dv, acc);  // self loop
        acc = fmaxf(acc + b1[j], 0.f);                           // bias + relu
        g_out1[(size_t)warp * HID + j] = acc;
    }
}

// -------- layer-2 aggregation fused with GEMM2 + bias + log_softmax --------
__global__ void gather2_softmax_kernel(const float* __restrict__ W2,
                                       const float* __restrict__ b2,
                                       float* __restrict__ out) {
    __shared__ float W2s[HID * N_CLS];
    __shared__ float b2s[N_CLS];
    for (int i = threadIdx.x; i < HID * N_CLS; i += blockDim.x) W2s[i] = W2[i];
    if (threadIdx.x < N_CLS) b2s[threadIdx.x] = b2[threadIdx.x];
    __syncthreads();

    int warp = (blockIdx.x * blockDim.x + threadIdx.x) >> 5;
    if (warp >= N_NODES) return;
    int lane = threadIdx.x & 31;
    int j = lane & 15;
    int p = lane >> 4;

    int beg = g_off[warp];
    int end = g_off[warp + 1];

    float a0 = 0.f, a1 = 0.f, a2 = 0.f, a3 = 0.f;
    int e = beg + p;
    for (; e + 6 < end; e += 8) {
        int2 r0 = g_csr[e];
        int2 r1 = g_csr[e + 2];
        int2 r2 = g_csr[e + 4];
        int2 r3 = g_csr[e + 6];
        a0 = fmaf(g_out1[(size_t)r0.x * HID + j], __int_as_float(r0.y), a0);
        a1 = fmaf(g_out1[(size_t)r1.x * HID + j], __int_as_float(r1.y), a1);
        a2 = fmaf(g_out1[(size_t)r2.x * HID + j], __int_as_float(r2.y), a2);
        a3 = fmaf(g_out1[(size_t)r3.x * HID + j], __int_as_float(r3.y), a3);
    }
    for (; e < end; e += 2) {
        int2 r0 = g_csr[e];
        a0 = fmaf(g_out1[(size_t)r0.x * HID + j], __int_as_float(r0.y), a0);
    }
    float av = (a0 + a1) + (a2 + a3);
    av += __shfl_xor_sync(0xffffffffu, av, 16);   // both halves now hold full sum
    float dv = g_dinv[warp];
    av = fmaf(g_out1[(size_t)warp * HID + j], dv * dv, av);  // self loop

    // av[j] replicated on lanes j and j+16. mat-vec 16x40 + log_softmax.
    bool act = lane < 20;
    int  j0  = act ? lane : 0;

    float z0 = 0.f, z1 = 0.f;
    #pragma unroll
    for (int k = 0; k < HID; k++) {
        float ak = __shfl_sync(0xffffffffu, av, k);   // lane k holds av[k]
        z0 = fmaf(ak, W2s[k * N_CLS + j0],      z0);
        z1 = fmaf(ak, W2s[k * N_CLS + j0 + 20], z1);
    }
    z0 += b2s[j0];
    z1 += b2s[j0 + 20];

    float m = act ? fmaxf(z0, z1) : -INFINITY;
    #pragma unroll
    for (int o = 16; o; o >>= 1) m = fmaxf(m, __shfl_xor_sync(0xffffffffu, m, o));
    float s = act ? (expf(z0 - m) + expf(z1 - m)) : 0.f;
    #pragma unroll
    for (int o = 16; o; o >>= 1) s += __shfl_xor_sync(0xffffffffu, s, o);
    float lse = m + logf(s);

    if (act) {
        out[(size_t)warp * N_CLS + lane]      = z0 - lse;
        out[(size_t)warp * N_CLS + lane + 20] = z1 - lse;
    }
}

// -------- launch --------
extern "C" void kernel_launch(void* const* d_in, const int* in_sizes, int n_in,
                              void* d_out, int out_size) {
    const float* x  = (const float*)d_in[0];
    const int*   ei = (const int*)d_in[1];     // int32 (JAX x64 disabled)
    const float* W1 = (const float*)d_in[2];
    const float* b1 = (const float*)d_in[3];
    const float* W2 = (const float*)d_in[4];
    const float* b2 = (const float*)d_in[5];
    float* out = (float*)d_out;

    cudaFuncSetAttribute(gemm1_kernel,
                         cudaFuncAttributeMaxDynamicSharedMemorySize, G1_SMEM);

    const int TB = 256;
    int nblk_nodes = (N_NODES + TB - 1) / TB;
    int nblk_edges = (E_EDGES + TB - 1) / TB;
    int nblk_gemm1 = (N_NODES + G1_ROWS - 1) / G1_ROWS;      // 1563
    int nblk_rows  = (N_NODES + (TB / 32) - 1) / (TB / 32);  // warp per node

    init_deg_kernel<<<nblk_nodes, TB>>>();
    hist_kernel<<<nblk_edges, TB>>>(ei);
    dinv_kernel<<<nblk_nodes, TB>>>();

    gemm1_kernel<<<nblk_gemm1, TB, G1_SMEM>>>(x, W1);   // launch #4 -> profiled

    scan_bsum_kernel<<<SCAN_NBLK, SCAN_TB>>>();
    scan_bpre_kernel<<<1, 512>>>();
    scan_off_kernel<<<SCAN_NBLK, SCAN_TB>>>();
    fill_kernel<<<nblk_edges, TB>>>(ei);

    gather1_kernel<<<nblk_rows, TB>>>(b1);
    gather2_softmax_kernel<<<nblk_rows, TB>>>(W2, b2, out);
}